// round 15
// baseline (speedup 1.0000x reference)
#include <cuda_runtime.h>
#include <cuda_fp16.h>
#include <cstdint>
#include <math.h>

#define MTOK 4096
#define HDIM 2048
#define NEXP 8
#define MOEI 1408
#define SHI  5632
#define CAP  4096

#define BM 128
#define BNO 64                                   // output-tile N (CTA 128x64)
#define BKH 64                                   // halves per K-slab (128 B/row)
#define NSTAGE 3
#define A_ST_BYTES (128 * 128)                   // 16384
#define STAGE_BYTES ((128 + 64) * 128)           // 24576
#define SMEM_TOTAL  (NSTAGE * STAGE_BYTES)       // 73728 -> 3 CTAs/SM

// merged gate_up grid decode (32-wide output tiles)
#define NBX_SH (SHI / 32)                        // 176
#define NBY    (MTOK / BM)                       // 32
#define NB_SH  (NBX_SH * NBY)                    // 5632
#define NBX_EX (MOEI / 32)                       // 44
#define NB_EXP (NBX_EX * NBY)                    // 1408 per expert
#define NB_GU  (NB_SH + NEXP * NB_EXP)           // 16896

// ---------------- static device scratch ----------------
__device__ __half g_xh  [(size_t)MTOK * HDIM];
__device__ __half g_sguwh[(size_t)(2 * SHI) * HDIM];
__device__ __half g_sdwh[(size_t)HDIM * SHI];
__device__ __half g_w13h[(size_t)NEXP * (2 * MOEI) * HDIM];
__device__ __half g_w2h [(size_t)NEXP * HDIM * MOEI];
__device__ __half g_actS[(size_t)MTOK * SHI];
__device__ __half g_eact[(size_t)NEXP * CAP * MOEI];
__device__ float  g_gateS[MTOK];
__device__ int    g_counts[NEXP];
__device__ int    g_perm [NEXP * CAP];
__device__ float  g_wslot[NEXP * CAP];

// ---------------- PTX helpers ----------------
__device__ __forceinline__ uint32_t smem_u32(const void* p) {
    uint32_t a;
    asm("{ .reg .u64 t; cvta.to.shared.u64 t, %1; cvt.u32.u64 %0, t; }" : "=r"(a) : "l"(p));
    return a;
}
#define CP16(dst, src) \
    asm volatile("cp.async.cg.shared.global [%0], [%1], 16;" :: "r"(dst), "l"(src))
#define CP_COMMIT() asm volatile("cp.async.commit_group;" ::: "memory")
#define CP_WAIT(n)  asm volatile("cp.async.wait_group %0;" :: "n"(n) : "memory")

__device__ __forceinline__ void mma_f16(float* c, const uint32_t* a, const uint32_t* b) {
    asm volatile(
        "mma.sync.aligned.m16n8k16.row.col.f32.f16.f16.f32 "
        "{%0,%1,%2,%3}, {%4,%5,%6,%7}, {%8,%9}, {%0,%1,%2,%3};"
        : "+f"(c[0]), "+f"(c[1]), "+f"(c[2]), "+f"(c[3])
        : "r"(a[0]), "r"(a[1]), "r"(a[2]), "r"(a[3]), "r"(b[0]), "r"(b[1]));
}

// ---------------- fused fp16 convert ----------------
#define SEG0 ((long)MTOK * HDIM / 8)
#define SEG1 (SEG0 + (long)(2 * SHI) * HDIM / 8)
#define SEG2 (SEG1 + (long)HDIM * SHI / 8)
#define SEG3 (SEG2 + (long)NEXP * (2 * MOEI) * HDIM / 8)
#define SEG4 (SEG3 + (long)NEXP * HDIM * MOEI / 8)
#define CVT_GRID ((unsigned)((SEG4 + 255) / 256))

__device__ __forceinline__ void cvt8(const float* in, __half* out, long i) {
    float4 v0 = ((const float4*)in)[2 * i];
    float4 v1 = ((const float4*)in)[2 * i + 1];
    __half2 h0 = __floats2half2_rn(v0.x, v0.y);
    __half2 h1 = __floats2half2_rn(v0.z, v0.w);
    __half2 h2 = __floats2half2_rn(v1.x, v1.y);
    __half2 h3 = __floats2half2_rn(v1.z, v1.w);
    uint4 o;
    o.x = *(uint32_t*)&h0; o.y = *(uint32_t*)&h1;
    o.z = *(uint32_t*)&h2; o.w = *(uint32_t*)&h3;
    ((uint4*)out)[i] = o;
}

__global__ void cvt_all_kernel(const float* __restrict__ x, const float* __restrict__ sguw,
                               const float* __restrict__ sdw, const float* __restrict__ w13,
                               const float* __restrict__ w2)
{
    long i = (long)blockIdx.x * blockDim.x + threadIdx.x;
    if (i >= SEG4) return;
    if      (i < SEG0) cvt8(x,    g_xh,    i);
    else if (i < SEG1) cvt8(sguw, g_sguwh, i - SEG0);
    else if (i < SEG2) cvt8(sdw,  g_sdwh,  i - SEG1);
    else if (i < SEG3) cvt8(w13,  g_w13h,  i - SEG2);
    else               cvt8(w2,   g_w2h,   i - SEG3);
}

// ---------------- small kernels ----------------
__global__ void init_kernel() {
    if (threadIdx.x < NEXP) g_counts[threadIdx.x] = 0;
}

__global__ void router_kernel(const float* __restrict__ x,
                              const float* __restrict__ gate_w,
                              const float* __restrict__ shared_gate_w)
{
    int m = blockIdx.x, tid = threadIdx.x, w = tid >> 5, lane = tid & 31;
    const float* xr = x + (size_t)m * HDIM;
    __shared__ float s_log[NEXP];
    __shared__ float s_sg;
    {
        const float* gw = gate_w + (size_t)w * HDIM;
        float sum = 0.f;
        for (int k = lane; k < HDIM; k += 32) sum += xr[k] * gw[k];
        #pragma unroll
        for (int o = 16; o; o >>= 1) sum += __shfl_xor_sync(0xffffffffu, sum, o);
        if (lane == 0) s_log[w] = sum;
    }
    if (w == 0) {
        float sg = 0.f;
        for (int k = lane; k < HDIM; k += 32) sg += xr[k] * shared_gate_w[k];
        #pragma unroll
        for (int o = 16; o; o >>= 1) sg += __shfl_xor_sync(0xffffffffu, sg, o);
        if (lane == 0) s_sg = sg;
    }
    __syncthreads();
    if (tid == 0) {
        float mx = -1e30f;
        #pragma unroll
        for (int e = 0; e < NEXP; e++) mx = fmaxf(mx, s_log[e]);
        float p[NEXP]; float den = 0.f;
        #pragma unroll
        for (int e = 0; e < NEXP; e++) { p[e] = expf(s_log[e] - mx); den += p[e]; }
        float inv = 1.f / den;
        int i1 = 0; float p1 = -1.f;
        #pragma unroll
        for (int e = 0; e < NEXP; e++) if (p[e] > p1) { p1 = p[e]; i1 = e; }
        int i2 = -1; float p2 = -1.f;
        #pragma unroll
        for (int e = 0; e < NEXP; e++) { if (e == i1) continue; if (p[e] > p2) { p2 = p[e]; i2 = e; } }
        p1 *= inv; p2 *= inv;
        g_gateS[m] = 1.f / (1.f + expf(-s_sg));
        int pos1 = atomicAdd(&g_counts[i1], 1);
        g_perm [i1 * CAP + pos1] = m;
        g_wslot[i1 * CAP + pos1] = p1;
        int pos2 = atomicAdd(&g_counts[i2], 1);
        g_perm [i2 * CAP + pos2] = m;
        g_wslot[i2 * CAP + pos2] = p2;
    }
}

// ---------------- fp16 mma.sync GEMM: 256 thr, 8 warps (4Mx2N), warp tile 32x32, CTA 128x64 ----------------
// MODE 0: merged gate_up (shared + experts, flattened blockIdx.x); fp16 silu*mul epilogue (32 cols).
// MODE 1: shared down: out(float) = (actS·sdw^T) * sigmoid-gate, plain store.
// MODE 2: expert down: out(float) += wslot * (eact·w2^T), atomicAdd epilogue.
template<int MODE>
__global__ __launch_bounds__(256, 3)
void mma_gemm(const __half* __restrict__ A0, const __half* __restrict__ W0,
              const __half* __restrict__ W1,
              void* __restrict__ C0, void* __restrict__ C1,
              const int* __restrict__ counts, const int* __restrict__ perm,
              const float* __restrict__ wslot, const float* __restrict__ rowScale)
{
    constexpr int K  = (MODE == 0) ? HDIM : (MODE == 1 ? SHI : MOEI);
    constexpr int KI = K / BKH;

    int e = 0, bx, by, cnt, I;
    const __half* A; const __half* W;
    __half* Ch = nullptr;
    const int* pm = nullptr;
    int n0g = 0;

    if (MODE == 0) {
        int bid = blockIdx.x;
        if (bid < NB_SH) {
            bx = bid % NBX_SH; by = bid / NBX_SH;
            I = SHI; cnt = MTOK;
            A = A0; W = W0; Ch = (__half*)C0;
        } else {
            int t = bid - NB_SH;
            e = t / NB_EXP; int rr = t % NB_EXP;
            bx = rr % NBX_EX; by = rr / NBX_EX;
            I = MOEI; cnt = counts[e];
            A = A0;
            W = W1 + (long)e * (2 * MOEI) * HDIM;
            Ch = (__half*)C1 + (long)e * CAP * MOEI;
            pm = perm + e * CAP;
        }
        n0g = bx * 32;
    } else if (MODE == 1) {
        bx = blockIdx.x; by = blockIdx.y;
        I = HDIM; cnt = MTOK;
        A = A0; W = W0;
    } else {
        e = blockIdx.z;
        bx = blockIdx.x; by = blockIdx.y;
        I = HDIM; cnt = counts[e];
        A = A0 + (long)e * CAP * MOEI;
        W = W0 + (long)e * HDIM * MOEI;
    }
    int m0 = by * BM;
    if (m0 >= cnt) return;

    extern __shared__ __half smem[];
    uint32_t smem_b = smem_u32(smem);

    int tid = threadIdx.x;
    int lane = tid & 31, wid = tid >> 5;
    int warpM = wid & 3, warpN = wid >> 2;

    // ---- producer A: row lr = tid>>1 (0..127), 32-half chunk ach = tid&1 (4x CP16) ----
    int lr = tid >> 1;
    int ach = tid & 1;
    int gr = m0 + lr;
    long arow = pm ? (long)((gr < cnt) ? pm[gr] : 0) : (long)((gr < cnt) ? gr : 0);
    const __half* aptr = A + arow * (long)K + ach * 32;
    uint32_t a_xor = (uint32_t)(lr & 7) << 4;
    uint32_t a_dst = smem_b + (uint32_t)lr * 128u;
    uint32_t kb    = (uint32_t)ach * 64u;

    // ---- producer B: rows 0..63, threads 0..127 ----
    bool bvalid = tid < 128;
    int br = tid >> 1;                           // reuse lr for tid<128
    long wrow;
    if (MODE == 0) {
        wrow = (br < 32) ? (long)(n0g + br) : (long)(I + n0g + (br - 32));
    } else {
        wrow = (long)(bx * BNO + br);
    }
    const __half* bptr = W + wrow * (long)K + ach * 32;
    uint32_t b_xor = (uint32_t)(br & 7) << 4;
    uint32_t b_dst = smem_b + (uint32_t)A_ST_BYTES + (uint32_t)br * 128u;

    // prologue: stages 0..NSTAGE-2
    #pragma unroll
    for (int s = 0; s < NSTAGE - 1; s++) {
        uint32_t so = (uint32_t)s * STAGE_BYTES;
        const __half* a = aptr + s * BKH;
        #pragma unroll
        for (int j = 0; j < 4; j++) CP16(a_dst + so + ((kb + j * 16) ^ a_xor), a + j * 8);
        if (bvalid) {
            const __half* b = bptr + s * BKH;
            #pragma unroll
            for (int j = 0; j < 4; j++) CP16(b_dst + so + ((kb + j * 16) ^ b_xor), b + j * 8);
        }
        CP_COMMIT();
    }

    float acc[2][4][4];
    #pragma unroll
    for (int i = 0; i < 2; i++)
        #pragma unroll
        for (int j = 0; j < 4; j++)
            #pragma unroll
            for (int q = 0; q < 4; q++) acc[i][j][q] = 0.f;

    int r = lane >> 2, cq = lane & 3;
    uint32_t rx = (uint32_t)(r & 7) << 4;        // read swizzle (bytes)
    uint32_t cqb = (uint32_t)cq * 4u;

    #pragma unroll 1
    for (int k = 0; k < KI; k++) {
        if (k <= KI - NSTAGE) { CP_WAIT(NSTAGE - 2); } else { CP_WAIT(0); }
        __syncthreads();

        int kn = k + NSTAGE - 1;
        if (kn < KI) {
            uint32_t so = (uint32_t)(kn % NSTAGE) * STAGE_BYTES;
            const __half* a = aptr + kn * BKH;
            #pragma unroll
            for (int j = 0; j < 4; j++) CP16(a_dst + so + ((kb + j * 16) ^ a_xor), a + j * 8);
            if (bvalid) {
                const __half* b = bptr + kn * BKH;
                #pragma unroll
                for (int j = 0; j < 4; j++) CP16(b_dst + so + ((kb + j * 16) ^ b_xor), b + j * 8);
            }
            CP_COMMIT();
        }

        uint32_t stA = smem_b + (uint32_t)(k % NSTAGE) * STAGE_BYTES;
        uint32_t stB = stA + (uint32_t)A_ST_BYTES;

        // 4 chunks of k16 per BK=64 halves
        #pragma unroll
        for (int c = 0; c < 4; c++) {
            uint32_t lo = (uint32_t)c * 32u;
            uint32_t hi = lo + 16u;
            uint32_t af[2][4], bf[4][2];
            #pragma unroll
            for (int mt = 0; mt < 2; mt++) {
                int mb = warpM * 32 + mt * 16;
                uint32_t r0 = stA + (uint32_t)(mb + r) * 128u;
                uint32_t r1 = stA + (uint32_t)(mb + 8 + r) * 128u;
                asm volatile("ld.shared.b32 %0, [%1];" : "=r"(af[mt][0]) : "r"(r0 + (lo ^ rx) + cqb));
                asm volatile("ld.shared.b32 %0, [%1];" : "=r"(af[mt][1]) : "r"(r1 + (lo ^ rx) + cqb));
                asm volatile("ld.shared.b32 %0, [%1];" : "=r"(af[mt][2]) : "r"(r0 + (hi ^ rx) + cqb));
                asm volatile("ld.shared.b32 %0, [%1];" : "=r"(af[mt][3]) : "r"(r1 + (hi ^ rx) + cqb));
            }
            #pragma unroll
            for (int nt = 0; nt < 4; nt++) {
                int nb = warpN * 32 + nt * 8;
                uint32_t rn = stB + (uint32_t)(nb + r) * 128u;
                asm volatile("ld.shared.b32 %0, [%1];" : "=r"(bf[nt][0]) : "r"(rn + (lo ^ rx) + cqb));
                asm volatile("ld.shared.b32 %0, [%1];" : "=r"(bf[nt][1]) : "r"(rn + (hi ^ rx) + cqb));
            }
            #pragma unroll
            for (int mt = 0; mt < 2; mt++)
                #pragma unroll
                for (int nt = 0; nt < 4; nt++)
                    mma_f16(acc[mt][nt], af[mt], bf[nt]);
        }
    }

    if (MODE == 1) {
        float* C = (float*)C0;
        int n0 = bx * BNO;
        int c2 = cq * 2;
        #pragma unroll
        for (int mt = 0; mt < 2; mt++) {
            #pragma unroll
            for (int half = 0; half < 2; half++) {
                int row = m0 + warpM * 32 + mt * 16 + half * 8 + r;
                if (row >= cnt) continue;
                float sc = rowScale[row];
                float* crow = C + (long)row * HDIM + n0 + warpN * 32;
                #pragma unroll
                for (int nt = 0; nt < 4; nt++) {
                    float2 v;
                    v.x = acc[mt][nt][half * 2 + 0] * sc;
                    v.y = acc[mt][nt][half * 2 + 1] * sc;
                    *(float2*)(crow + nt * 8 + c2) = v;
                }
            }
        }
    } else if (MODE == 2) {
        float* C = (float*)C0;
        int n0 = bx * BNO;
        int c2 = cq * 2;
        #pragma unroll
        for (int mt = 0; mt < 2; mt++) {
            #pragma unroll
            for (int half = 0; half < 2; half++) {
                int row = m0 + warpM * 32 + mt * 16 + half * 8 + r;
                if (row >= cnt) continue;
                int   tok = perm [e * CAP + row];
                float wgt = wslot[e * CAP + row];
                float* crow = C + (long)tok * HDIM + n0 + warpN * 32;
                #pragma unroll
                for (int nt = 0; nt < 4; nt++) {
                    atomicAdd(crow + nt * 8 + c2 + 0, acc[mt][nt][half * 2 + 0] * wgt);
                    atomicAdd(crow + nt * 8 + c2 + 1, acc[mt][nt][half * 2 + 1] * wgt);
                }
            }
        }
    } else {
        // MODE 0: stage accumulators through smem to pair gate/up columns
        __syncthreads();
        float* Cs = (float*)smem;                // [128][68] floats = 34816 B <= SMEM_TOTAL
        int c2 = cq * 2;
        #pragma unroll
        for (int mt = 0; mt < 2; mt++)
            #pragma unroll
            for (int half = 0; half < 2; half++) {
                int rr = warpM * 32 + mt * 16 + half * 8 + r;
                #pragma unroll
                for (int nt = 0; nt < 4; nt++) {
                    float2 v;
                    v.x = acc[mt][nt][half * 2 + 0];
                    v.y = acc[mt][nt][half * 2 + 1];
                    *(float2*)(Cs + rr * 68 + warpN * 32 + nt * 8 + c2) = v;
                }
            }
        __syncthreads();
        int row = tid >> 1;
        int cb = (tid & 1) * 16;
        if (m0 + row < cnt) {
            __half* crow = Ch + (long)(m0 + row) * I + n0g;
            #pragma unroll
            for (int j = 0; j < 16; j += 4) {
                float4 g = *(const float4*)(Cs + row * 68 + cb + j);
                float4 u = *(const float4*)(Cs + row * 68 + 32 + cb + j);
                float o0 = g.x / (1.f + __expf(-g.x)) * u.x;
                float o1 = g.y / (1.f + __expf(-g.y)) * u.y;
                float o2 = g.z / (1.f + __expf(-g.z)) * u.z;
                float o3 = g.w / (1.f + __expf(-g.w)) * u.w;
                __half2 h0 = __floats2half2_rn(o0, o1);
                __half2 h1 = __floats2half2_rn(o2, o3);
                uint2 pk;
                pk.x = *(uint32_t*)&h0;
                pk.y = *(uint32_t*)&h1;
                *(uint2*)(crow + cb + j) = pk;
            }
        }
    }
}

// ---------------- launch ----------------
extern "C" void kernel_launch(void* const* d_in, const int* in_sizes, int n_in,
                              void* d_out, int out_size)
{
    (void)in_sizes; (void)n_in; (void)out_size;
    const float* x    = (const float*)d_in[0];
    const float* gw   = (const float*)d_in[1];
    const float* sgw  = (const float*)d_in[2];
    const float* sguw = (const float*)d_in[3];
    const float* sdw  = (const float*)d_in[4];
    const float* w13  = (const float*)d_in[5];
    const float* w2   = (const float*)d_in[6];
    float* out = (float*)d_out;

    __half *xh, *sguwh, *sdwh, *w13h, *w2h, *actS, *eact;
    float *gateS, *wslot;
    int *counts, *perm;
    cudaGetSymbolAddress((void**)&xh,     g_xh);
    cudaGetSymbolAddress((void**)&sguwh,  g_sguwh);
    cudaGetSymbolAddress((void**)&sdwh,   g_sdwh);
    cudaGetSymbolAddress((void**)&w13h,   g_w13h);
    cudaGetSymbolAddress((void**)&w2h,    g_w2h);
    cudaGetSymbolAddress((void**)&actS,   g_actS);
    cudaGetSymbolAddress((void**)&eact,   g_eact);
    cudaGetSymbolAddress((void**)&gateS,  g_gateS);
    cudaGetSymbolAddress((void**)&counts, g_counts);
    cudaGetSymbolAddress((void**)&perm,   g_perm);
    cudaGetSymbolAddress((void**)&wslot,  g_wslot);

    cudaFuncSetAttribute(mma_gemm<0>, cudaFuncAttributeMaxDynamicSharedMemorySize, SMEM_TOTAL);
    cudaFuncSetAttribute(mma_gemm<1>, cudaFuncAttributeMaxDynamicSharedMemorySize, SMEM_TOTAL);
    cudaFuncSetAttribute(mma_gemm<2>, cudaFuncAttributeMaxDynamicSharedMemorySize, SMEM_TOTAL);

    init_kernel<<<1, 32>>>();
    router_kernel<<<MTOK, 256>>>(x, gw, sgw);
    cvt_all_kernel<<<CVT_GRID, 256>>>(x, sguw, sdw, w13, w2);

    // merged gate_up: shared (silu*mul -> actS) + experts (gathered -> eact)
    mma_gemm<0><<<NB_GU, 256, SMEM_TOTAL>>>(
        xh, sguwh, w13h, actS, eact, counts, perm, nullptr, nullptr);
    // shared down: out = (actS·sdw^T)*sigmoid  (plain store)
    mma_gemm<1><<<dim3(HDIM / BNO, MTOK / BM, 1), 256, SMEM_TOTAL>>>(
        actS, sdwh, nullptr, out, nullptr, nullptr, nullptr, nullptr, gateS);
    // expert down: out += wslot * (eact·w2^T)  (atomicAdd)
    mma_gemm<2><<<dim3(HDIM / BNO, CAP / BM, NEXP), 256, SMEM_TOTAL>>>(
        eact, w2h, nullptr, out, nullptr, counts, perm, wslot, nullptr);
}

// round 16
// speedup vs baseline: 1.1935x; 1.1935x over previous
#include <cuda_runtime.h>
#include <cuda_fp16.h>
#include <cstdint>
#include <math.h>

#define MTOK 4096
#define HDIM 2048
#define NEXP 8
#define MOEI 1408
#define SHI  5632
#define CAP  4096

#define BM 128
#define BN 128
#define BKH 64                                   // halves per K-slab (128 B/row)
#define NSTAGE 3
#define A_ST_BYTES (128 * 128)                   // 16384
#define STAGE_BYTES (2 * 128 * 128)              // 32768
#define SMEM_TOTAL  (NSTAGE * STAGE_BYTES)       // 98304 -> 2 CTAs/SM

// merged gate_up grid decode (64-wide output tiles)
#define NBX_SH (SHI / 64)                        // 88
#define NBY    (MTOK / BM)                       // 32
#define NB_SH  (NBX_SH * NBY)                    // 2816
#define NBX_EX (MOEI / 64)                       // 22
#define NB_EXP (NBX_EX * NBY)                    // 704 per expert
#define NB_GU  (NB_SH + NEXP * NB_EXP)           // 8448

// ---------------- static device scratch ----------------
__device__ __half g_xh  [(size_t)MTOK * HDIM];
__device__ __half g_sguwh[(size_t)(2 * SHI) * HDIM];
__device__ __half g_sdwh[(size_t)HDIM * SHI];
__device__ __half g_w13h[(size_t)NEXP * (2 * MOEI) * HDIM];
__device__ __half g_w2h [(size_t)NEXP * HDIM * MOEI];
__device__ __half g_actS[(size_t)MTOK * SHI];
__device__ __half g_eact[(size_t)NEXP * CAP * MOEI];
__device__ float  g_gateS[MTOK];
__device__ int    g_counts[NEXP];
__device__ int    g_perm [NEXP * CAP];
__device__ float  g_wslot[NEXP * CAP];

// ---------------- PTX helpers ----------------
__device__ __forceinline__ uint32_t smem_u32(const void* p) {
    uint32_t a;
    asm("{ .reg .u64 t; cvta.to.shared.u64 t, %1; cvt.u32.u64 %0, t; }" : "=r"(a) : "l"(p));
    return a;
}
#define CP16(dst, src) \
    asm volatile("cp.async.cg.shared.global [%0], [%1], 16;" :: "r"(dst), "l"(src))
#define CP_COMMIT() asm volatile("cp.async.commit_group;" ::: "memory")
#define CP_WAIT(n)  asm volatile("cp.async.wait_group %0;" :: "n"(n) : "memory")

__device__ __forceinline__ void mma_f16(float* c, const uint32_t* a, const uint32_t* b) {
    asm volatile(
        "mma.sync.aligned.m16n8k16.row.col.f32.f16.f16.f32 "
        "{%0,%1,%2,%3}, {%4,%5,%6,%7}, {%8,%9}, {%0,%1,%2,%3};"
        : "+f"(c[0]), "+f"(c[1]), "+f"(c[2]), "+f"(c[3])
        : "r"(a[0]), "r"(a[1]), "r"(a[2]), "r"(a[3]), "r"(b[0]), "r"(b[1]));
}

// ---------------- fused fp16 convert ----------------
#define SEG0 ((long)MTOK * HDIM / 8)
#define SEG1 (SEG0 + (long)(2 * SHI) * HDIM / 8)
#define SEG2 (SEG1 + (long)HDIM * SHI / 8)
#define SEG3 (SEG2 + (long)NEXP * (2 * MOEI) * HDIM / 8)
#define SEG4 (SEG3 + (long)NEXP * HDIM * MOEI / 8)
#define CVT_GRID ((unsigned)((SEG4 + 255) / 256))

__device__ __forceinline__ void cvt8(const float* in, __half* out, long i) {
    float4 v0 = ((const float4*)in)[2 * i];
    float4 v1 = ((const float4*)in)[2 * i + 1];
    __half2 h0 = __floats2half2_rn(v0.x, v0.y);
    __half2 h1 = __floats2half2_rn(v0.z, v0.w);
    __half2 h2 = __floats2half2_rn(v1.x, v1.y);
    __half2 h3 = __floats2half2_rn(v1.z, v1.w);
    uint4 o;
    o.x = *(uint32_t*)&h0; o.y = *(uint32_t*)&h1;
    o.z = *(uint32_t*)&h2; o.w = *(uint32_t*)&h3;
    ((uint4*)out)[i] = o;
}

__global__ void cvt_all_kernel(const float* __restrict__ x, const float* __restrict__ sguw,
                               const float* __restrict__ sdw, const float* __restrict__ w13,
                               const float* __restrict__ w2)
{
    long i = (long)blockIdx.x * blockDim.x + threadIdx.x;
    if (i >= SEG4) return;
    if      (i < SEG0) cvt8(x,    g_xh,    i);
    else if (i < SEG1) cvt8(sguw, g_sguwh, i - SEG0);
    else if (i < SEG2) cvt8(sdw,  g_sdwh,  i - SEG1);
    else if (i < SEG3) cvt8(w13,  g_w13h,  i - SEG2);
    else               cvt8(w2,   g_w2h,   i - SEG3);
}

// ---------------- small kernels ----------------
__global__ void init_kernel() {
    if (threadIdx.x < NEXP) g_counts[threadIdx.x] = 0;
}

__global__ void router_kernel(const float* __restrict__ x,
                              const float* __restrict__ gate_w,
                              const float* __restrict__ shared_gate_w)
{
    int m = blockIdx.x, tid = threadIdx.x, w = tid >> 5, lane = tid & 31;
    const float* xr = x + (size_t)m * HDIM;
    __shared__ float s_log[NEXP];
    __shared__ float s_sg;
    {
        const float* gw = gate_w + (size_t)w * HDIM;
        float sum = 0.f;
        for (int k = lane; k < HDIM; k += 32) sum += xr[k] * gw[k];
        #pragma unroll
        for (int o = 16; o; o >>= 1) sum += __shfl_xor_sync(0xffffffffu, sum, o);
        if (lane == 0) s_log[w] = sum;
    }
    if (w == 0) {
        float sg = 0.f;
        for (int k = lane; k < HDIM; k += 32) sg += xr[k] * shared_gate_w[k];
        #pragma unroll
        for (int o = 16; o; o >>= 1) sg += __shfl_xor_sync(0xffffffffu, sg, o);
        if (lane == 0) s_sg = sg;
    }
    __syncthreads();
    if (tid == 0) {
        float mx = -1e30f;
        #pragma unroll
        for (int e = 0; e < NEXP; e++) mx = fmaxf(mx, s_log[e]);
        float p[NEXP]; float den = 0.f;
        #pragma unroll
        for (int e = 0; e < NEXP; e++) { p[e] = expf(s_log[e] - mx); den += p[e]; }
        float inv = 1.f / den;
        int i1 = 0; float p1 = -1.f;
        #pragma unroll
        for (int e = 0; e < NEXP; e++) if (p[e] > p1) { p1 = p[e]; i1 = e; }
        int i2 = -1; float p2 = -1.f;
        #pragma unroll
        for (int e = 0; e < NEXP; e++) { if (e == i1) continue; if (p[e] > p2) { p2 = p[e]; i2 = e; } }
        p1 *= inv; p2 *= inv;
        g_gateS[m] = 1.f / (1.f + expf(-s_sg));
        int pos1 = atomicAdd(&g_counts[i1], 1);
        g_perm [i1 * CAP + pos1] = m;
        g_wslot[i1 * CAP + pos1] = p1;
        int pos2 = atomicAdd(&g_counts[i2], 1);
        g_perm [i2 * CAP + pos2] = m;
        g_wslot[i2 * CAP + pos2] = p2;
    }
}

// ---------------- fp16 mma.sync GEMM: 128 thr, 4 warps (2Mx2N), warp tile 64x64, CTA 128x128 ----------------
// MODE 0: merged gate_up (shared + experts, flattened blockIdx.x); fp16 silu*mul epilogue (64 cols).
// MODE 1: shared down: out(float) = (actS·sdw^T) * sigmoid-gate, plain store.
// MODE 2: expert down: out(float) += wslot * (eact·w2^T), atomicAdd epilogue.
template<int MODE>
__global__ __launch_bounds__(128, 2)
void mma_gemm(const __half* __restrict__ A0, const __half* __restrict__ W0,
              const __half* __restrict__ W1,
              void* __restrict__ C0, void* __restrict__ C1,
              const int* __restrict__ counts, const int* __restrict__ perm,
              const float* __restrict__ wslot, const float* __restrict__ rowScale)
{
    constexpr int K  = (MODE == 0) ? HDIM : (MODE == 1 ? SHI : MOEI);
    constexpr int KI = K / BKH;

    int e = 0, bx, by, cnt, I;
    const __half* A; const __half* W;
    __half* Ch = nullptr;
    const int* pm = nullptr;
    int n0g = 0;

    if (MODE == 0) {
        int bid = blockIdx.x;
        if (bid < NB_SH) {
            bx = bid % NBX_SH; by = bid / NBX_SH;
            I = SHI; cnt = MTOK;
            A = A0; W = W0; Ch = (__half*)C0;
        } else {
            int t = bid - NB_SH;
            e = t / NB_EXP; int rr = t % NB_EXP;
            bx = rr % NBX_EX; by = rr / NBX_EX;
            I = MOEI; cnt = counts[e];
            A = A0;
            W = W1 + (long)e * (2 * MOEI) * HDIM;
            Ch = (__half*)C1 + (long)e * CAP * MOEI;
            pm = perm + e * CAP;
        }
        n0g = bx * 64;
    } else if (MODE == 1) {
        bx = blockIdx.x; by = blockIdx.y;
        I = HDIM; cnt = MTOK;
        A = A0; W = W0;
    } else {
        e = blockIdx.z;
        bx = blockIdx.x; by = blockIdx.y;
        I = HDIM; cnt = counts[e];
        A = A0 + (long)e * CAP * MOEI;
        W = W0 + (long)e * HDIM * MOEI;
    }
    int m0 = by * BM;
    if (m0 >= cnt) return;

    extern __shared__ __half smem[];
    uint32_t smem_b = smem_u32(smem);

    int tid = threadIdx.x;
    int lane = tid & 31, wid = tid >> 5;
    int warpM = wid & 1, warpN = wid >> 1;

    // ---- producer: thread t fills full A row tid and full B row tid (8x CP16 each) ----
    int lr = tid;
    int gr = m0 + lr;
    long arow = pm ? (long)((gr < cnt) ? pm[gr] : 0) : (long)((gr < cnt) ? gr : 0);
    const __half* aptr = A + arow * (long)K;
    long wrow;
    if (MODE == 0) {
        wrow = (lr < 64) ? (long)(n0g + lr) : (long)(I + n0g + (lr - 64));
    } else {
        wrow = (long)(bx * BN + lr);
    }
    const __half* bptr = W + wrow * (long)K;
    uint32_t xb = (uint32_t)(lr & 7) << 4;               // write swizzle (bytes)
    uint32_t a_dst = smem_b + (uint32_t)lr * 128u;
    uint32_t b_dst = a_dst + (uint32_t)A_ST_BYTES;

    // prologue: stages 0..NSTAGE-2
    #pragma unroll
    for (int s = 0; s < NSTAGE - 1; s++) {
        uint32_t so = (uint32_t)s * STAGE_BYTES;
        const __half* a = aptr + s * BKH;
        const __half* b = bptr + s * BKH;
        #pragma unroll
        for (int j = 0; j < 8; j++) CP16(a_dst + so + ((j * 16) ^ xb), a + j * 8);
        #pragma unroll
        for (int j = 0; j < 8; j++) CP16(b_dst + so + ((j * 16) ^ xb), b + j * 8);
        CP_COMMIT();
    }

    float acc[4][8][4];
    #pragma unroll
    for (int i = 0; i < 4; i++)
        #pragma unroll
        for (int j = 0; j < 8; j++)
            #pragma unroll
            for (int q = 0; q < 4; q++) acc[i][j][q] = 0.f;

    int r = lane >> 2, cq = lane & 3;
    uint32_t rx  = (uint32_t)(r & 7) << 4;               // read swizzle (bytes)
    uint32_t cqb = (uint32_t)cq * 4u;

    #pragma unroll 1
    for (int k = 0; k < KI; k++) {
        if (k <= KI - NSTAGE) { CP_WAIT(NSTAGE - 2); } else { CP_WAIT(0); }
        __syncthreads();

        int kn = k + NSTAGE - 1;
        if (kn < KI) {
            uint32_t so = (uint32_t)(kn % NSTAGE) * STAGE_BYTES;
            const __half* a = aptr + kn * BKH;
            const __half* b = bptr + kn * BKH;
            #pragma unroll
            for (int j = 0; j < 8; j++) CP16(a_dst + so + ((j * 16) ^ xb), a + j * 8);
            #pragma unroll
            for (int j = 0; j < 8; j++) CP16(b_dst + so + ((j * 16) ^ xb), b + j * 8);
            CP_COMMIT();
        }

        uint32_t stA = smem_b + (uint32_t)(k % NSTAGE) * STAGE_BYTES;
        uint32_t stB = stA + (uint32_t)A_ST_BYTES;

        // 4 chunks of k16 per BK=64 halves
        #pragma unroll
        for (int c = 0; c < 4; c++) {
            uint32_t lo = (uint32_t)c * 32u;
            uint32_t hi = lo + 16u;
            uint32_t af[4][4], bf[8][2];
            #pragma unroll
            for (int mt = 0; mt < 4; mt++) {
                int mb = warpM * 64 + mt * 16;
                uint32_t r0 = stA + (uint32_t)(mb + r) * 128u;
                uint32_t r1 = stA + (uint32_t)(mb + 8 + r) * 128u;
                asm volatile("ld.shared.b32 %0, [%1];" : "=r"(af[mt][0]) : "r"(r0 + (lo ^ rx) + cqb));
                asm volatile("ld.shared.b32 %0, [%1];" : "=r"(af[mt][1]) : "r"(r1 + (lo ^ rx) + cqb));
                asm volatile("ld.shared.b32 %0, [%1];" : "=r"(af[mt][2]) : "r"(r0 + (hi ^ rx) + cqb));
                asm volatile("ld.shared.b32 %0, [%1];" : "=r"(af[mt][3]) : "r"(r1 + (hi ^ rx) + cqb));
            }
            #pragma unroll
            for (int nt = 0; nt < 8; nt++) {
                int nb = warpN * 64 + nt * 8;
                uint32_t rn = stB + (uint32_t)(nb + r) * 128u;
                asm volatile("ld.shared.b32 %0, [%1];" : "=r"(bf[nt][0]) : "r"(rn + (lo ^ rx) + cqb));
                asm volatile("ld.shared.b32 %0, [%1];" : "=r"(bf[nt][1]) : "r"(rn + (hi ^ rx) + cqb));
            }
            #pragma unroll
            for (int mt = 0; mt < 4; mt++)
                #pragma unroll
                for (int nt = 0; nt < 8; nt++)
                    mma_f16(acc[mt][nt], af[mt], bf[nt]);
        }
    }

    if (MODE == 1) {
        float* C = (float*)C0;
        int n0 = bx * BN;
        int c2 = cq * 2;
        #pragma unroll
        for (int mt = 0; mt < 4; mt++) {
            #pragma unroll
            for (int half = 0; half < 2; half++) {
                int row = m0 + warpM * 64 + mt * 16 + half * 8 + r;
                if (row >= cnt) continue;
                float sc = rowScale[row];
                float* crow = C + (long)row * HDIM + n0 + warpN * 64;
                #pragma unroll
                for (int nt = 0; nt < 8; nt++) {
                    float2 v;
                    v.x = acc[mt][nt][half * 2 + 0] * sc;
                    v.y = acc[mt][nt][half * 2 + 1] * sc;
                    *(float2*)(crow + nt * 8 + c2) = v;
                }
            }
        }
    } else if (MODE == 2) {
        float* C = (float*)C0;
        int n0 = bx * BN;
        int c2 = cq * 2;
        #pragma unroll
        for (int mt = 0; mt < 4; mt++) {
            #pragma unroll
            for (int half = 0; half < 2; half++) {
                int row = m0 + warpM * 64 + mt * 16 + half * 8 + r;
                if (row >= cnt) continue;
                int   tok = perm [e * CAP + row];
                float wgt = wslot[e * CAP + row];
                float* crow = C + (long)tok * HDIM + n0 + warpN * 64;
                #pragma unroll
                for (int nt = 0; nt < 8; nt++) {
                    atomicAdd(crow + nt * 8 + c2 + 0, acc[mt][nt][half * 2 + 0] * wgt);
                    atomicAdd(crow + nt * 8 + c2 + 1, acc[mt][nt][half * 2 + 1] * wgt);
                }
            }
        }
    } else {
        // MODE 0: stage accumulators through smem to pair gate/up columns
        __syncthreads();
        float* Cs = (float*)smem;                // [128][132] floats = 67584 B <= SMEM_TOTAL
        int c2 = cq * 2;
        #pragma unroll
        for (int mt = 0; mt < 4; mt++)
            #pragma unroll
            for (int half = 0; half < 2; half++) {
                int rr = warpM * 64 + mt * 16 + half * 8 + r;
                #pragma unroll
                for (int nt = 0; nt < 8; nt++) {
                    float2 v;
                    v.x = acc[mt][nt][half * 2 + 0];
                    v.y = acc[mt][nt][half * 2 + 1];
                    *(float2*)(Cs + rr * 132 + warpN * 64 + nt * 8 + c2) = v;
                }
            }
        __syncthreads();
        int row = tid;
        if (m0 + row < cnt) {
            __half* crow = Ch + (long)(m0 + row) * I + n0g;
            #pragma unroll
            for (int j = 0; j < 64; j += 4) {
                float4 g = *(const float4*)(Cs + row * 132 + j);
                float4 u = *(const float4*)(Cs + row * 132 + 64 + j);
                float o0 = g.x / (1.f + __expf(-g.x)) * u.x;
                float o1 = g.y / (1.f + __expf(-g.y)) * u.y;
                float o2 = g.z / (1.f + __expf(-g.z)) * u.z;
                float o3 = g.w / (1.f + __expf(-g.w)) * u.w;
                __half2 h0 = __floats2half2_rn(o0, o1);
                __half2 h1 = __floats2half2_rn(o2, o3);
                uint2 pk;
                pk.x = *(uint32_t*)&h0;
                pk.y = *(uint32_t*)&h1;
                *(uint2*)(crow + j) = pk;
            }
        }
    }
}

// ---------------- launch ----------------
extern "C" void kernel_launch(void* const* d_in, const int* in_sizes, int n_in,
                              void* d_out, int out_size)
{
    (void)in_sizes; (void)n_in; (void)out_size;
    const float* x    = (const float*)d_in[0];
    const float* gw   = (const float*)d_in[1];
    const float* sgw  = (const float*)d_in[2];
    const float* sguw = (const float*)d_in[3];
    const float* sdw  = (const float*)d_in[4];
    const float* w13  = (const float*)d_in[5];
    const float* w2   = (const float*)d_in[6];
    float* out = (float*)d_out;

    __half *xh, *sguwh, *sdwh, *w13h, *w2h, *actS, *eact;
    float *gateS, *wslot;
    int *counts, *perm;
    cudaGetSymbolAddress((void**)&xh,     g_xh);
    cudaGetSymbolAddress((void**)&sguwh,  g_sguwh);
    cudaGetSymbolAddress((void**)&sdwh,   g_sdwh);
    cudaGetSymbolAddress((void**)&w13h,   g_w13h);
    cudaGetSymbolAddress((void**)&w2h,    g_w2h);
    cudaGetSymbolAddress((void**)&actS,   g_actS);
    cudaGetSymbolAddress((void**)&eact,   g_eact);
    cudaGetSymbolAddress((void**)&gateS,  g_gateS);
    cudaGetSymbolAddress((void**)&counts, g_counts);
    cudaGetSymbolAddress((void**)&perm,   g_perm);
    cudaGetSymbolAddress((void**)&wslot,  g_wslot);

    cudaFuncSetAttribute(mma_gemm<0>, cudaFuncAttributeMaxDynamicSharedMemorySize, SMEM_TOTAL);
    cudaFuncSetAttribute(mma_gemm<1>, cudaFuncAttributeMaxDynamicSharedMemorySize, SMEM_TOTAL);
    cudaFuncSetAttribute(mma_gemm<2>, cudaFuncAttributeMaxDynamicSharedMemorySize, SMEM_TOTAL);

    init_kernel<<<1, 32>>>();
    router_kernel<<<MTOK, 256>>>(x, gw, sgw);
    cvt_all_kernel<<<CVT_GRID, 256>>>(x, sguw, sdw, w13, w2);

    // merged gate_up: shared (silu*mul -> actS) + experts (gathered -> eact)
    mma_gemm<0><<<NB_GU, 128, SMEM_TOTAL>>>(
        xh, sguwh, w13h, actS, eact, counts, perm, nullptr, nullptr);
    // shared down: out = (actS·sdw^T)*sigmoid  (plain store)
    mma_gemm<1><<<dim3(HDIM / BN, MTOK / BM, 1), 128, SMEM_TOTAL>>>(
        actS, sdwh, nullptr, out, nullptr, nullptr, nullptr, nullptr, gateS);
    // expert down: out += wslot * (eact·w2^T)  (atomicAdd)
    mma_gemm<2><<<dim3(HDIM / BN, CAP / BM, NEXP), 128, SMEM_TOTAL>>>(
        eact, w2h, nullptr, out, nullptr, counts, perm, wslot, nullptr);
}

// round 17
// speedup vs baseline: 1.7417x; 1.4593x over previous
#include <cuda_runtime.h>
#include <cuda_fp16.h>
#include <cstdint>
#include <math.h>

#define MTOK 4096
#define HDIM 2048
#define NEXP 8
#define MOEI 1408
#define SHI  5632
#define CAP  4096

#define BM 128
#define BN 128
#define BKH 64                                   // halves per K-slab (128 B/row)
#define NSTAGE 3
#define STAGE_BYTES  (2 * 128 * 128)             // A tile + B tile (128 rows x 128B each)
#define SMEM_TOTAL   (NSTAGE * STAGE_BYTES)      // 98304 -> 2 CTAs/SM

// merged gate_up grid decode
#define NBX_SH (SHI / 64)                        // 88
#define NBY    (MTOK / BM)                       // 32
#define NB_SH  (NBX_SH * NBY)                    // 2816
#define NBX_EX (MOEI / 64)                       // 22
#define NB_EXP (NBX_EX * NBY)                    // 704 per expert
#define NB_GU  (NB_SH + NEXP * NB_EXP)           // 8448

// merged down grid decode
#define NBX_DN (HDIM / BN)                       // 16
#define NB_DSH (NBX_DN * NBY)                    // 512 (shared down)
#define NB_DEX (NBX_DN * NBY)                    // 512 per expert
#define NB_DN  (NB_DSH + NEXP * NB_DEX)          // 4608

// ---------------- static device scratch ----------------
__device__ __half g_xh  [(size_t)MTOK * HDIM];
__device__ __half g_sguwh[(size_t)(2 * SHI) * HDIM];
__device__ __half g_sdwh[(size_t)HDIM * SHI];
__device__ __half g_w13h[(size_t)NEXP * (2 * MOEI) * HDIM];
__device__ __half g_w2h [(size_t)NEXP * HDIM * MOEI];
__device__ __half g_actS[(size_t)MTOK * SHI];
__device__ __half g_eact[(size_t)NEXP * CAP * MOEI];
__device__ float  g_gateS[MTOK];
__device__ int    g_counts[NEXP];
__device__ int    g_perm [NEXP * CAP];
__device__ float  g_wslot[NEXP * CAP];

// ---------------- PTX helpers ----------------
__device__ __forceinline__ uint32_t smem_u32(const void* p) {
    uint32_t a;
    asm("{ .reg .u64 t; cvta.to.shared.u64 t, %1; cvt.u32.u64 %0, t; }" : "=r"(a) : "l"(p));
    return a;
}
#define CP16(dst, src) \
    asm volatile("cp.async.cg.shared.global [%0], [%1], 16;" :: "r"(dst), "l"(src))
#define CP_COMMIT() asm volatile("cp.async.commit_group;" ::: "memory")
#define CP_WAIT(n)  asm volatile("cp.async.wait_group %0;" :: "n"(n) : "memory")

__device__ __forceinline__ void mma_f16(float* c, const uint32_t* a, const uint32_t* b) {
    asm volatile(
        "mma.sync.aligned.m16n8k16.row.col.f32.f16.f16.f32 "
        "{%0,%1,%2,%3}, {%4,%5,%6,%7}, {%8,%9}, {%0,%1,%2,%3};"
        : "+f"(c[0]), "+f"(c[1]), "+f"(c[2]), "+f"(c[3])
        : "r"(a[0]), "r"(a[1]), "r"(a[2]), "r"(a[3]), "r"(b[0]), "r"(b[1]));
}

// ---------------- fused fp16 convert ----------------
#define SEG0 ((long)MTOK * HDIM / 8)
#define SEG1 (SEG0 + (long)(2 * SHI) * HDIM / 8)
#define SEG2 (SEG1 + (long)HDIM * SHI / 8)
#define SEG3 (SEG2 + (long)NEXP * (2 * MOEI) * HDIM / 8)
#define SEG4 (SEG3 + (long)NEXP * HDIM * MOEI / 8)
#define CVT_GRID ((unsigned)((SEG4 + 255) / 256))

__device__ __forceinline__ void cvt8(const float* in, __half* out, long i) {
    float4 v0 = ((const float4*)in)[2 * i];
    float4 v1 = ((const float4*)in)[2 * i + 1];
    __half2 h0 = __floats2half2_rn(v0.x, v0.y);
    __half2 h1 = __floats2half2_rn(v0.z, v0.w);
    __half2 h2 = __floats2half2_rn(v1.x, v1.y);
    __half2 h3 = __floats2half2_rn(v1.z, v1.w);
    uint4 o;
    o.x = *(uint32_t*)&h0; o.y = *(uint32_t*)&h1;
    o.z = *(uint32_t*)&h2; o.w = *(uint32_t*)&h3;
    ((uint4*)out)[i] = o;
}

__global__ void cvt_all_kernel(const float* __restrict__ x, const float* __restrict__ sguw,
                               const float* __restrict__ sdw, const float* __restrict__ w13,
                               const float* __restrict__ w2)
{
    long i = (long)blockIdx.x * blockDim.x + threadIdx.x;
    if (i >= SEG4) return;
    if      (i < SEG0) cvt8(x,    g_xh,    i);
    else if (i < SEG1) cvt8(sguw, g_sguwh, i - SEG0);
    else if (i < SEG2) cvt8(sdw,  g_sdwh,  i - SEG1);
    else if (i < SEG3) cvt8(w13,  g_w13h,  i - SEG2);
    else               cvt8(w2,   g_w2h,   i - SEG3);
}

// ---------------- small kernels ----------------
__global__ void init_kernel() {
    if (threadIdx.x < NEXP) g_counts[threadIdx.x] = 0;
}

__global__ void router_kernel(const float* __restrict__ x,
                              const float* __restrict__ gate_w,
                              const float* __restrict__ shared_gate_w)
{
    int m = blockIdx.x, tid = threadIdx.x, w = tid >> 5, lane = tid & 31;
    const float* xr = x + (size_t)m * HDIM;
    __shared__ float s_log[NEXP];
    __shared__ float s_sg;
    {
        const float* gw = gate_w + (size_t)w * HDIM;
        float sum = 0.f;
        for (int k = lane; k < HDIM; k += 32) sum += xr[k] * gw[k];
        #pragma unroll
        for (int o = 16; o; o >>= 1) sum += __shfl_xor_sync(0xffffffffu, sum, o);
        if (lane == 0) s_log[w] = sum;
    }
    if (w == 0) {
        float sg = 0.f;
        for (int k = lane; k < HDIM; k += 32) sg += xr[k] * shared_gate_w[k];
        #pragma unroll
        for (int o = 16; o; o >>= 1) sg += __shfl_xor_sync(0xffffffffu, sg, o);
        if (lane == 0) s_sg = sg;
    }
    __syncthreads();
    if (tid == 0) {
        float mx = -1e30f;
        #pragma unroll
        for (int e = 0; e < NEXP; e++) mx = fmaxf(mx, s_log[e]);
        float p[NEXP]; float den = 0.f;
        #pragma unroll
        for (int e = 0; e < NEXP; e++) { p[e] = expf(s_log[e] - mx); den += p[e]; }
        float inv = 1.f / den;
        int i1 = 0; float p1 = -1.f;
        #pragma unroll
        for (int e = 0; e < NEXP; e++) if (p[e] > p1) { p1 = p[e]; i1 = e; }
        int i2 = -1; float p2 = -1.f;
        #pragma unroll
        for (int e = 0; e < NEXP; e++) { if (e == i1) continue; if (p[e] > p2) { p2 = p[e]; i2 = e; } }
        p1 *= inv; p2 *= inv;
        g_gateS[m] = 1.f / (1.f + expf(-s_sg));
        int pos1 = atomicAdd(&g_counts[i1], 1);
        g_perm [i1 * CAP + pos1] = m;
        g_wslot[i1 * CAP + pos1] = p1;
        int pos2 = atomicAdd(&g_counts[i2], 1);
        g_perm [i2 * CAP + pos2] = m;
        g_wslot[i2 * CAP + pos2] = p2;
    }
}

// ---------------- fp16 mma.sync GEMM: 256 thr, 8 warps (4Mx2N), warp tile 32x64 ----------------
// MODE 0: merged gate_up (shared + experts via flattened blockIdx.x); fp16 silu*mul epilogue.
// MODE 2: merged down (shared + experts): out(float) += weight * (A·W^T), atomicAdd epilogue.
template<int MODE>
__global__ __launch_bounds__(256, 2)
void mma_gemm(const __half* __restrict__ A0, const __half* __restrict__ W0,
              const __half* __restrict__ W1,
              void* __restrict__ C0, void* __restrict__ C1,
              const int* __restrict__ counts, const int* __restrict__ perm,
              const float* __restrict__ wslot, const float* __restrict__ rowScale)
{
    int e = 0, bx, by, cnt, I, K;
    const __half* A; const __half* W;
    __half* Ch = nullptr;
    const int* pm = nullptr;
    bool shared_part = false;
    int n0g = 0;

    if (MODE == 0) {
        K = HDIM;
        int bid = blockIdx.x;
        if (bid < NB_SH) {
            bx = bid % NBX_SH; by = bid / NBX_SH;
            I = SHI; cnt = MTOK;
            A = A0; W = W0; Ch = (__half*)C0;
        } else {
            int t = bid - NB_SH;
            e = t / NB_EXP; int rr = t % NB_EXP;
            bx = rr % NBX_EX; by = rr / NBX_EX;
            I = MOEI; cnt = counts[e];
            A = A0;
            W = W1 + (long)e * (2 * MOEI) * HDIM;
            Ch = (__half*)C1 + (long)e * CAP * MOEI;
            pm = perm + e * CAP;
        }
        n0g = bx * 64;
    } else {
        I = HDIM;
        int bid = blockIdx.x;
        if (bid < NB_DSH) {
            bx = bid % NBX_DN; by = bid / NBX_DN;
            K = SHI; cnt = MTOK;
            A = A0; W = W0;
            shared_part = true;
        } else {
            int t = bid - NB_DSH;
            e = t / NB_DEX; int rr = t % NB_DEX;
            bx = rr % NBX_DN; by = rr / NBX_DN;
            K = MOEI; cnt = counts[e];
            A = (const __half*)C1 + (long)e * CAP * MOEI;   // eact
            W = W1 + (long)e * HDIM * MOEI;                 // w2h
        }
    }
    int m0 = by * BM;
    if (m0 >= cnt) return;
    int KI = K / BKH;

    extern __shared__ __half smem[];
    uint32_t smem_b = smem_u32(smem);

    int tid = threadIdx.x;
    int lane = tid & 31, wid = tid >> 5;
    int warpM = wid & 3, warpN = wid >> 2;

    // ---- producer: thread t fills row lr = tid>>1, 32-half chunk ach = tid&1 (4x CP16) ----
    int lr = tid >> 1;
    int ach = tid & 1;
    int gr = m0 + lr;
    long arow = pm ? (long)((gr < cnt) ? pm[gr] : 0) : (long)((gr < cnt) ? gr : 0);
    const __half* aptr = A + arow * (long)K + ach * 32;
    long wrow;
    if (MODE == 0) {
        wrow = (lr < 64) ? (long)(n0g + lr) : (long)(I + n0g + (lr - 64));
    } else {
        wrow = (long)(bx * BN + lr);
    }
    const __half* bptr = W + wrow * (long)K + ach * 32;
    uint32_t xb = (uint32_t)(lr & 7) << 4;               // write swizzle (bytes)
    uint32_t arow_b = smem_b + (uint32_t)lr * 128u;
    uint32_t brow_b = arow_b + 128u * 128u;
    uint32_t kb = (uint32_t)ach * 64u;

    // prologue: stages 0..NSTAGE-2
    #pragma unroll
    for (int s = 0; s < NSTAGE - 1; s++) {
        const __half* a = aptr + s * BKH;
        const __half* b = bptr + s * BKH;
        uint32_t so = (uint32_t)s * STAGE_BYTES;
        #pragma unroll
        for (int j = 0; j < 4; j++) CP16(arow_b + so + ((kb + j * 16) ^ xb), a + j * 8);
        #pragma unroll
        for (int j = 0; j < 4; j++) CP16(brow_b + so + ((kb + j * 16) ^ xb), b + j * 8);
        CP_COMMIT();
    }

    float acc[2][8][4];
    #pragma unroll
    for (int i = 0; i < 2; i++)
        #pragma unroll
        for (int j = 0; j < 8; j++)
            #pragma unroll
            for (int q = 0; q < 4; q++) acc[i][j][q] = 0.f;

    int r = lane >> 2, cq = lane & 3;
    uint32_t rx = (uint32_t)(r & 7) << 4;                // read swizzle (bytes)
    uint32_t cqb = (uint32_t)cq * 4u;

    #pragma unroll 1
    for (int k = 0; k < KI; k++) {
        if (k <= KI - NSTAGE) { CP_WAIT(NSTAGE - 2); } else { CP_WAIT(0); }
        __syncthreads();

        int kn = k + NSTAGE - 1;
        if (kn < KI) {
            const __half* a = aptr + kn * BKH;
            const __half* b = bptr + kn * BKH;
            uint32_t so = (uint32_t)(kn % NSTAGE) * STAGE_BYTES;
            #pragma unroll
            for (int j = 0; j < 4; j++) CP16(arow_b + so + ((kb + j * 16) ^ xb), a + j * 8);
            #pragma unroll
            for (int j = 0; j < 4; j++) CP16(brow_b + so + ((kb + j * 16) ^ xb), b + j * 8);
            CP_COMMIT();
        }

        uint32_t stA = smem_b + (uint32_t)(k % NSTAGE) * STAGE_BYTES;
        uint32_t stB = stA + 128u * 128u;

        // 4 chunks of k16 per BK=64 halves
        #pragma unroll
        for (int c = 0; c < 4; c++) {
            uint32_t lo = (uint32_t)c * 32u;
            uint32_t hi = lo + 16u;
            uint32_t af[2][4], bf[8][2];
            #pragma unroll
            for (int mt = 0; mt < 2; mt++) {
                int mb = warpM * 32 + mt * 16;
                uint32_t r0 = stA + (uint32_t)(mb + r) * 128u;
                uint32_t r1 = stA + (uint32_t)(mb + 8 + r) * 128u;
                asm volatile("ld.shared.b32 %0, [%1];" : "=r"(af[mt][0]) : "r"(r0 + (lo ^ rx) + cqb));
                asm volatile("ld.shared.b32 %0, [%1];" : "=r"(af[mt][1]) : "r"(r1 + (lo ^ rx) + cqb));
                asm volatile("ld.shared.b32 %0, [%1];" : "=r"(af[mt][2]) : "r"(r0 + (hi ^ rx) + cqb));
                asm volatile("ld.shared.b32 %0, [%1];" : "=r"(af[mt][3]) : "r"(r1 + (hi ^ rx) + cqb));
            }
            #pragma unroll
            for (int nt = 0; nt < 8; nt++) {
                int nb = warpN * 64 + nt * 8;
                uint32_t rn = stB + (uint32_t)(nb + r) * 128u;
                asm volatile("ld.shared.b32 %0, [%1];" : "=r"(bf[nt][0]) : "r"(rn + (lo ^ rx) + cqb));
                asm volatile("ld.shared.b32 %0, [%1];" : "=r"(bf[nt][1]) : "r"(rn + (hi ^ rx) + cqb));
            }
            #pragma unroll
            for (int mt = 0; mt < 2; mt++)
                #pragma unroll
                for (int nt = 0; nt < 8; nt++)
                    mma_f16(acc[mt][nt], af[mt], bf[nt]);
        }
    }

    if (MODE == 2) {
        float* C = (float*)C0;
        int n0 = bx * BN;
        int c2 = cq * 2;
        #pragma unroll
        for (int mt = 0; mt < 2; mt++) {
            #pragma unroll
            for (int half = 0; half < 2; half++) {
                int row = m0 + warpM * 32 + mt * 16 + half * 8 + r;
                if (row >= cnt) continue;
                int tok; float wgt;
                if (shared_part) { tok = row;                 wgt = rowScale[row]; }
                else             { tok = perm [e * CAP + row]; wgt = wslot[e * CAP + row]; }
                float* crow = C + (long)tok * HDIM + n0 + warpN * 64;
                #pragma unroll
                for (int nt = 0; nt < 8; nt++) {
                    atomicAdd(crow + nt * 8 + c2 + 0, acc[mt][nt][half * 2 + 0] * wgt);
                    atomicAdd(crow + nt * 8 + c2 + 1, acc[mt][nt][half * 2 + 1] * wgt);
                }
            }
        }
    } else {
        // MODE 0: stage accumulators through smem to pair gate/up columns
        __syncthreads();
        float* Cs = (float*)smem;            // [128][132] floats = 67584 B <= SMEM_TOTAL
        int c2 = cq * 2;
        #pragma unroll
        for (int mt = 0; mt < 2; mt++)
            #pragma unroll
            for (int half = 0; half < 2; half++) {
                int rr = warpM * 32 + mt * 16 + half * 8 + r;
                #pragma unroll
                for (int nt = 0; nt < 8; nt++) {
                    float2 v;
                    v.x = acc[mt][nt][half * 2 + 0];
                    v.y = acc[mt][nt][half * 2 + 1];
                    *(float2*)(Cs + rr * 132 + warpN * 64 + nt * 8 + c2) = v;
                }
            }
        __syncthreads();
        int row = tid >> 1;
        int cb = (tid & 1) * 32;
        if (m0 + row < cnt) {
            __half* crow = Ch + (long)(m0 + row) * I + n0g;
            #pragma unroll
            for (int j = 0; j < 32; j += 4) {
                float4 g = *(const float4*)(Cs + row * 132 + cb + j);
                float4 u = *(const float4*)(Cs + row * 132 + 64 + cb + j);
                float o0 = g.x / (1.f + __expf(-g.x)) * u.x;
                float o1 = g.y / (1.f + __expf(-g.y)) * u.y;
                float o2 = g.z / (1.f + __expf(-g.z)) * u.z;
                float o3 = g.w / (1.f + __expf(-g.w)) * u.w;
                __half2 h0 = __floats2half2_rn(o0, o1);
                __half2 h1 = __floats2half2_rn(o2, o3);
                uint2 pk;
                pk.x = *(uint32_t*)&h0;
                pk.y = *(uint32_t*)&h1;
                *(uint2*)(crow + cb + j) = pk;
            }
        }
    }
}

// ---------------- launch ----------------
extern "C" void kernel_launch(void* const* d_in, const int* in_sizes, int n_in,
                              void* d_out, int out_size)
{
    (void)in_sizes; (void)n_in; (void)out_size;
    const float* x    = (const float*)d_in[0];
    const float* gw   = (const float*)d_in[1];
    const float* sgw  = (const float*)d_in[2];
    const float* sguw = (const float*)d_in[3];
    const float* sdw  = (const float*)d_in[4];
    const float* w13  = (const float*)d_in[5];
    const float* w2   = (const float*)d_in[6];
    float* out = (float*)d_out;

    __half *xh, *sguwh, *sdwh, *w13h, *w2h, *actS, *eact;
    float *gateS, *wslot;
    int *counts, *perm;
    cudaGetSymbolAddress((void**)&xh,     g_xh);
    cudaGetSymbolAddress((void**)&sguwh,  g_sguwh);
    cudaGetSymbolAddress((void**)&sdwh,   g_sdwh);
    cudaGetSymbolAddress((void**)&w13h,   g_w13h);
    cudaGetSymbolAddress((void**)&w2h,    g_w2h);
    cudaGetSymbolAddress((void**)&actS,   g_actS);
    cudaGetSymbolAddress((void**)&eact,   g_eact);
    cudaGetSymbolAddress((void**)&gateS,  g_gateS);
    cudaGetSymbolAddress((void**)&counts, g_counts);
    cudaGetSymbolAddress((void**)&perm,   g_perm);
    cudaGetSymbolAddress((void**)&wslot,  g_wslot);

    cudaFuncSetAttribute(mma_gemm<0>, cudaFuncAttributeMaxDynamicSharedMemorySize, SMEM_TOTAL);
    cudaFuncSetAttribute(mma_gemm<2>, cudaFuncAttributeMaxDynamicSharedMemorySize, SMEM_TOTAL);

    init_kernel<<<1, 32>>>();
    router_kernel<<<MTOK, 256>>>(x, gw, sgw);
    cvt_all_kernel<<<CVT_GRID, 256>>>(x, sguw, sdw, w13, w2);
    cudaMemsetAsync(out, 0, (size_t)MTOK * HDIM * sizeof(float));

    // merged gate_up: shared (silu*mul -> actS) + experts (gathered -> eact)
    mma_gemm<0><<<NB_GU, 256, SMEM_TOTAL>>>(
        xh, sguwh, w13h, actS, eact, counts, perm, nullptr, nullptr);
    // merged down: out += sigmoid-gate * (actS·sdw^T)  and  out += wslot * (eact·w2^T)
    mma_gemm<2><<<NB_DN, 256, SMEM_TOTAL>>>(
        actS, sdwh, w2h, out, eact, counts, perm, wslot, gateS);
}